// round 13
// baseline (speedup 1.0000x reference)
#include <cuda_runtime.h>
#include <cstdint>

#define NB 32
#define NP 64
#define NV 32000
#define NROWS (NB * NP)
#define GRID_X 1216          // 152 SMs * 8 blocks/SM
#define NF4 (NV / 4)         // 8000 float4 per row
#define W0_START 7360        // warp 0 streams [7360, 8000) = 640 float4 (20/lane)
                             // warps 1..7 stream [0, 7360) (~33/lane)

// scratch (no allocations allowed)
__device__ float g_loss[NROWS];
__device__ int   g_ctr    = 0;   // work-stealing row counter
__device__ int   g_ticket = 0;   // last-block-finishes ticket

// ---------------------------------------------------------------------------
// Fused persistent kernel (R12 champion + warp-0 tail streaming).
//   warp 0      : Myers DP to row r + argmin truth set + dedup + gather sum,
//                 THEN streams the last 640 float4 of the row (its reduced
//                 share compensates the DP head start).
//   warps 1..7  : stream float4 row sum over [0, W0_START).
// Last block (ticket) reduces g_loss -> scalar and resets counters.
// ---------------------------------------------------------------------------
__global__ void __launch_bounds__(256) fused_kernel(
    const float* __restrict__ outputs,
    const int*   __restrict__ outsym,
    const int*   __restrict__ targets,
    const unsigned char* __restrict__ mask,
    float* __restrict__ out)
{
    const int tid = threadIdx.x;
    const int wid = tid >> 5;
    const int l   = tid & 31;

    __shared__ int    s_row;
    __shared__ int    tgt_s[64];
    __shared__ int    sym_s[64];
    __shared__ double red[8];
    __shared__ int    m_sh;
    __shared__ float  sumS_sh;
    __shared__ int    last_sh;

    for (;;) {
        if (tid == 0) s_row = atomicAdd(&g_ctr, 1);
        __syncthreads();
        const int row = s_row;
        if (row >= NROWS) break;

        const int b = row >> 6;
        const int r = row & 63;

        if (mask[row]) {
            const float* rowp = outputs + (size_t)row * NV;

            if (wid == 0) {
                // ---- metadata (per-batch, L2-hot) ----
                const int t_lo = targets[b * 64 + l];
                const int t_hi = targets[b * 64 + 32 + l];
                tgt_s[l]      = t_lo;
                tgt_s[32 + l] = t_hi;
                sym_s[l]      = outsym[b * 64 + l];
                sym_s[32 + l] = outsym[b * 64 + 32 + l];
                const unsigned mml = __ballot_sync(0xffffffffu, mask[b * 64 + l] != 0);
                const unsigned mmh = __ballot_sync(0xffffffffu, mask[b * 64 + 32 + l] != 0);
                const unsigned long long mm =
                    ((unsigned long long)mmh << 32) | (unsigned long long)mml;
                __syncwarp();

                // ---- Myers bit-vector DP up to row r ----
                unsigned long long VP = 0x7FFFFFFFFFFFFFFFull;   // row 0 = arange
                unsigned long long VN = 0ull;
                for (int i = 1; i <= r; i++) {
                    const int s = sym_s[i - 1];
                    const unsigned eql = __ballot_sync(0xffffffffu, t_lo == s);
                    const unsigned eqh = __ballot_sync(0xffffffffu, t_hi == s) & 0x7FFFFFFFu;
                    const unsigned long long Eq =
                        ((unsigned long long)eqh << 32) | (unsigned long long)eql;
                    const unsigned long long X  = Eq | VN;
                    const unsigned long long D0 = ((VP + (X & VP)) ^ VP) | X;
                    const unsigned long long HN = VP & D0;
                    const unsigned long long HP = VN | ~(VP | D0);
                    const unsigned long long X2 = (HP << 1) | 1ull;
                    VN = X2 & D0;
                    VP = (HN << 1) | ~(X2 | D0);
                }

                // ---- row profile: lane l owns columns l and l+32 ----
                const unsigned long long lm0 = (1ull << l) - 1ull;
                const unsigned long long lm1 = (1ull << (l + 32)) - 1ull;
                const int d0 = r + __popcll(VP & lm0) - __popcll(VN & lm0);
                const int d1 = r + __popcll(VP & lm1) - __popcll(VN & lm1);
                const int md0 = ((mm >> l) & 1ull)        ? d0 : 0x7fffffff;
                const int md1 = ((mm >> (l + 32)) & 1ull) ? d1 : 0x7fffffff;

                int mn = min(md0, md1);
                #pragma unroll
                for (int o = 16; o > 0; o >>= 1)
                    mn = min(mn, __shfl_xor_sync(0xffffffffu, mn, o));

                const unsigned cm_lo = __ballot_sync(0xffffffffu, md0 == mn);
                const unsigned cm_hi = __ballot_sync(0xffffffffu, md1 == mn);
                const unsigned long long CM =
                    ((unsigned long long)cm_hi << 32) | (unsigned long long)cm_lo;

                // ---- dedup: keep col c iff no earlier candidate has same vocab ----
                bool keep0 = (md0 == mn);
                if (keep0) {
                    unsigned long long e = CM & lm0;
                    while (e) {
                        const int c = __ffsll((long long)e) - 1;
                        e &= e - 1;
                        if (tgt_s[c] == t_lo) { keep0 = false; break; }
                    }
                }
                bool keep1 = (md1 == mn);
                if (keep1) {
                    unsigned long long e = CM & lm1;
                    while (e) {
                        const int c = __ffsll((long long)e) - 1;
                        e &= e - 1;
                        if (tgt_s[c] == t_hi) { keep1 = false; break; }
                    }
                }
                const unsigned k0 = __ballot_sync(0xffffffffu, keep0);
                const unsigned k1 = __ballot_sync(0xffffffffu, keep1);
                const int m = __popc(k0) + __popc(k1);

                // ---- gather sum over distinct truth set (L2-hot row) ----
                float s = 0.f;
                if (keep0) s += __ldg(rowp + t_lo);
                if (keep1) s += __ldg(rowp + t_hi);
                #pragma unroll
                for (int o = 16; o > 0; o >>= 1)
                    s += __shfl_xor_sync(0xffffffffu, s, o);
                if (l == 0) { m_sh = m; sumS_sh = s; }

                // ---- warp 0 streams the tail segment [W0_START, NF4) ----
                const float4* p = (const float4*)rowp;
                float s0 = 0.f, comp0 = 0.f;
                #pragma unroll 4
                for (int i = W0_START + l; i < NF4; i += 32) {
                    const float4 v = p[i];
                    const float t = (v.x + v.y) + (v.z + v.w);
                    const float y = t - comp0;
                    const float u = s0 + y;
                    comp0 = (u - s0) - y;
                    s0 = u;
                }
                double ds0 = (double)s0 - (double)comp0;
                #pragma unroll
                for (int o = 16; o > 0; o >>= 1)
                    ds0 += __shfl_xor_sync(0xffffffffu, ds0, o);
                if (l == 0) red[0] = ds0;
            } else {
                // ---- warps 1..7: stream [0, W0_START) (Kahan, double reduce) ----
                const float4* p = (const float4*)rowp;
                float s = 0.f, comp = 0.f;
                #pragma unroll 8
                for (int i = tid - 32; i < W0_START; i += 224) {
                    const float4 v = p[i];
                    const float t = (v.x + v.y) + (v.z + v.w);
                    const float y = t - comp;
                    const float u = s + y;
                    comp = (u - s) - y;
                    s = u;
                }
                double ds = (double)s - (double)comp;
                #pragma unroll
                for (int o = 16; o > 0; o >>= 1)
                    ds += __shfl_xor_sync(0xffffffffu, ds, o);
                if (l == 0) red[wid] = ds;
            }
            __syncthreads();

            if (tid == 0) {
                double tot = 0.0;
                #pragma unroll
                for (int w = 0; w < 8; w++) tot += red[w];

                const int    m    = m_sh;
                const double sumS = (double)sumS_sh;
                const double einv = 0.36787944117144233;          // e^-1
                const double D    = (double)m + (double)(NV - m) * einv;
                const double phi  = 1.0 / D;
                const double plo  = einv / D;
                const double kl   = (double)m * phi * log(phi)
                                  + (double)(NV - m) * plo * log(plo)
                                  - (plo * tot + (phi - plo) * sumS);
                g_loss[row] = (float)kl;
            }
        } else {
            if (tid == 0) g_loss[row] = 0.f;
        }
        __syncthreads();   // protects s_row / red / m_sh reuse
    }

    // ---- threadfence-ticket: last block does the final reduction ----
    if (tid == 0) {
        __threadfence();
        last_sh = (atomicAdd(&g_ticket, 1) == GRID_X - 1);
    }
    __syncthreads();

    if (last_sh) {
        __shared__ double pb_sh[32];
        __shared__ int    ne_sh[32];

        // thread t: batch bb = t>>3, chunk sub = t&7 (8 elements each)
        const int bb  = tid >> 3;
        const int sub = tid & 7;
        double ls = 0.0, w = 0.0;
        #pragma unroll
        for (int j = 0; j < 8; j++) {
            const int idx = bb * 64 + sub * 8 + j;
            ls += (double)g_loss[idx];
            w  += (mask[idx] != 0) ? 1.0 : 0.0;
        }
        #pragma unroll
        for (int o = 4; o > 0; o >>= 1) {
            ls += __shfl_xor_sync(0xffffffffu, ls, o);
            w  += __shfl_xor_sync(0xffffffffu, w,  o);
        }
        if (sub == 0) {
            pb_sh[bb] = ls / (w + 1e-13);
            ne_sh[bb] = (w > 0.0) ? 1 : 0;
        }
        __syncthreads();

        if (tid < 32) {
            double pb = pb_sh[tid];
            int    ne = ne_sh[tid];
            #pragma unroll
            for (int o = 16; o > 0; o >>= 1) {
                pb += __shfl_xor_sync(0xffffffffu, pb, o);
                ne += __shfl_xor_sync(0xffffffffu, ne, o);
            }
            if (tid == 0) {
                out[0] = (float)(pb / ((double)ne + 1e-13));
                g_ticket = 0;          // reset for next graph replay
                g_ctr    = 0;
            }
        }
    }
}

extern "C" void kernel_launch(void* const* d_in, const int* in_sizes, int n_in,
                              void* d_out, int out_size)
{
    const float* outputs        = (const float*)d_in[0];
    const int*   output_symbols = (const int*)d_in[1];
    const int*   targets        = (const int*)d_in[2];
    const unsigned char* mask   = (const unsigned char*)d_in[3];

    fused_kernel<<<GRID_X, 256>>>(outputs, output_symbols, targets, mask,
                                  (float*)d_out);
}

// round 14
// speedup vs baseline: 1.0199x; 1.0199x over previous
#include <cuda_runtime.h>
#include <cstdint>

#define NB 32
#define NP 64
#define NV 32000
#define NROWS (NB * NP)
#define GRID_X 1216          // 152 SMs * 8 blocks/SM -> single resident wave

// scratch (no allocations allowed)
__device__ float g_loss[NROWS];
__device__ int   g_ctr    = 0;   // work-stealing row counter
__device__ int   g_ticket = 0;   // last-block-finishes ticket

// ---------------------------------------------------------------------------
// Fused persistent kernel. Blocks steal rows (b,r) from g_ctr.
//   warp 0      : Myers bit-parallel edit-distance DP to row r, argmin truth
//                 set, distinct-vocab dedup, gather sum over the truth set.
//   warps 1..7  : streaming float4 row sum over V (the memory-bound part).
// Last block (ticket) reduces g_loss -> scalar and resets counters.
// ---------------------------------------------------------------------------
__global__ void __launch_bounds__(256) fused_kernel(
    const float* __restrict__ outputs,
    const int*   __restrict__ outsym,
    const int*   __restrict__ targets,
    const unsigned char* __restrict__ mask,
    float* __restrict__ out)
{
    const int tid = threadIdx.x;
    const int wid = tid >> 5;
    const int l   = tid & 31;

    __shared__ int    s_row;
    __shared__ int    tgt_s[64];
    __shared__ int    sym_s[64];
    __shared__ double red[8];
    __shared__ int    m_sh;
    __shared__ float  sumS_sh;
    __shared__ int    last_sh;

    for (;;) {
        if (tid == 0) s_row = atomicAdd(&g_ctr, 1);
        __syncthreads();
        const int row = s_row;
        if (row >= NROWS) break;

        const int b = row >> 6;
        const int r = row & 63;

        if (mask[row]) {
            if (wid == 0) {
                // ---- metadata (per-batch, L2-hot) ----
                const int t_lo = targets[b * 64 + l];
                const int t_hi = targets[b * 64 + 32 + l];
                tgt_s[l]      = t_lo;
                tgt_s[32 + l] = t_hi;
                sym_s[l]      = outsym[b * 64 + l];
                sym_s[32 + l] = outsym[b * 64 + 32 + l];
                const unsigned mml = __ballot_sync(0xffffffffu, mask[b * 64 + l] != 0);
                const unsigned mmh = __ballot_sync(0xffffffffu, mask[b * 64 + 32 + l] != 0);
                const unsigned long long mm =
                    ((unsigned long long)mmh << 32) | (unsigned long long)mml;
                __syncwarp();

                // ---- Myers bit-vector DP up to row r ----
                unsigned long long VP = 0x7FFFFFFFFFFFFFFFull;   // row 0 = arange
                unsigned long long VN = 0ull;
                for (int i = 1; i <= r; i++) {
                    const int s = sym_s[i - 1];
                    const unsigned eql = __ballot_sync(0xffffffffu, t_lo == s);
                    const unsigned eqh = __ballot_sync(0xffffffffu, t_hi == s) & 0x7FFFFFFFu;
                    const unsigned long long Eq =
                        ((unsigned long long)eqh << 32) | (unsigned long long)eql;
                    const unsigned long long X  = Eq | VN;
                    const unsigned long long D0 = ((VP + (X & VP)) ^ VP) | X;
                    const unsigned long long HN = VP & D0;
                    const unsigned long long HP = VN | ~(VP | D0);
                    const unsigned long long X2 = (HP << 1) | 1ull;
                    VN = X2 & D0;
                    VP = (HN << 1) | ~(X2 | D0);
                }

                // ---- row profile: lane l owns columns l and l+32 ----
                const unsigned long long lm0 = (1ull << l) - 1ull;
                const unsigned long long lm1 = (1ull << (l + 32)) - 1ull;
                const int d0 = r + __popcll(VP & lm0) - __popcll(VN & lm0);
                const int d1 = r + __popcll(VP & lm1) - __popcll(VN & lm1);
                const int md0 = ((mm >> l) & 1ull)        ? d0 : 0x7fffffff;
                const int md1 = ((mm >> (l + 32)) & 1ull) ? d1 : 0x7fffffff;

                int mn = min(md0, md1);
                #pragma unroll
                for (int o = 16; o > 0; o >>= 1)
                    mn = min(mn, __shfl_xor_sync(0xffffffffu, mn, o));

                const unsigned cm_lo = __ballot_sync(0xffffffffu, md0 == mn);
                const unsigned cm_hi = __ballot_sync(0xffffffffu, md1 == mn);
                const unsigned long long CM =
                    ((unsigned long long)cm_hi << 32) | (unsigned long long)cm_lo;

                // ---- dedup: keep col c iff no earlier candidate has same vocab ----
                bool keep0 = (md0 == mn);
                if (keep0) {
                    unsigned long long e = CM & lm0;
                    while (e) {
                        const int c = __ffsll((long long)e) - 1;
                        e &= e - 1;
                        if (tgt_s[c] == t_lo) { keep0 = false; break; }
                    }
                }
                bool keep1 = (md1 == mn);
                if (keep1) {
                    unsigned long long e = CM & lm1;
                    while (e) {
                        const int c = __ffsll((long long)e) - 1;
                        e &= e - 1;
                        if (tgt_s[c] == t_hi) { keep1 = false; break; }
                    }
                }
                const unsigned k0 = __ballot_sync(0xffffffffu, keep0);
                const unsigned k1 = __ballot_sync(0xffffffffu, keep1);
                const int m = __popc(k0) + __popc(k1);

                // ---- gather sum over distinct truth set (L2-hot row) ----
                const float* rowp = outputs + (size_t)row * NV;
                float s = 0.f;
                if (keep0) s += __ldg(rowp + t_lo);
                if (keep1) s += __ldg(rowp + t_hi);
                #pragma unroll
                for (int o = 16; o > 0; o >>= 1)
                    s += __shfl_xor_sync(0xffffffffu, s, o);

                if (l == 0) { m_sh = m; sumS_sh = s; }
            } else {
                // ---- streaming row sum (Kahan per thread, double reduce) ----
                const float4* p = (const float4*)(outputs + (size_t)row * NV);
                float s = 0.f, comp = 0.f;
                #pragma unroll 8
                for (int i = tid - 32; i < NV / 4; i += 224) {
                    const float4 v = p[i];
                    const float t = (v.x + v.y) + (v.z + v.w);
                    const float y = t - comp;
                    const float u = s + y;
                    comp = (u - s) - y;
                    s = u;
                }
                double ds = (double)s - (double)comp;
                #pragma unroll
                for (int o = 16; o > 0; o >>= 1)
                    ds += __shfl_xor_sync(0xffffffffu, ds, o);
                if (l == 0) red[wid] = ds;
            }
            __syncthreads();

            if (tid == 0) {
                double tot = 0.0;
                #pragma unroll
                for (int w = 1; w < 8; w++) tot += red[w];

                const int    m    = m_sh;
                const double sumS = (double)sumS_sh;
                const double einv = 0.36787944117144233;          // e^-1
                const double D    = (double)m + (double)(NV - m) * einv;
                const double phi  = 1.0 / D;
                const double plo  = einv / D;
                const double kl   = (double)m * phi * log(phi)
                                  + (double)(NV - m) * plo * log(plo)
                                  - (plo * tot + (phi - plo) * sumS);
                g_loss[row] = (float)kl;
            }
        } else {
            if (tid == 0) g_loss[row] = 0.f;
        }
        __syncthreads();   // protects s_row reuse next iteration
    }

    // ---- threadfence-ticket: last block does the final reduction ----
    if (tid == 0) {
        __threadfence();
        last_sh = (atomicAdd(&g_ticket, 1) == GRID_X - 1);
    }
    __syncthreads();

    if (last_sh) {
        __shared__ double pb_sh[32];
        __shared__ int    ne_sh[32];

        // thread t: batch bb = t>>3, chunk sub = t&7 (8 elements each)
        const int bb  = tid >> 3;
        const int sub = tid & 7;
        double ls = 0.0, w = 0.0;
        #pragma unroll
        for (int j = 0; j < 8; j++) {
            const int idx = bb * 64 + sub * 8 + j;
            ls += (double)g_loss[idx];
            w  += (mask[idx] != 0) ? 1.0 : 0.0;
        }
        #pragma unroll
        for (int o = 4; o > 0; o >>= 1) {
            ls += __shfl_xor_sync(0xffffffffu, ls, o);
            w  += __shfl_xor_sync(0xffffffffu, w,  o);
        }
        if (sub == 0) {
            pb_sh[bb] = ls / (w + 1e-13);
            ne_sh[bb] = (w > 0.0) ? 1 : 0;
        }
        __syncthreads();

        if (tid < 32) {
            double pb = pb_sh[tid];
            int    ne = ne_sh[tid];
            #pragma unroll
            for (int o = 16; o > 0; o >>= 1) {
                pb += __shfl_xor_sync(0xffffffffu, pb, o);
                ne += __shfl_xor_sync(0xffffffffu, ne, o);
            }
            if (tid == 0) {
                out[0] = (float)(pb / ((double)ne + 1e-13));
                g_ticket = 0;          // reset for next graph replay
                g_ctr    = 0;
            }
        }
    }
}

extern "C" void kernel_launch(void* const* d_in, const int* in_sizes, int n_in,
                              void* d_out, int out_size)
{
    const float* outputs        = (const float*)d_in[0];
    const int*   output_symbols = (const int*)d_in[1];
    const int*   targets        = (const int*)d_in[2];
    const unsigned char* mask   = (const unsigned char*)d_in[3];

    fused_kernel<<<GRID_X, 256>>>(outputs, output_symbols, targets, mask,
                                  (float*)d_out);
}